// round 15
// baseline (speedup 1.0000x reference)
#include <cuda_runtime.h>
#include <cuda_bf16.h>
#include <cuda_fp16.h>
#include <cstdint>

#define NPIX 262144
#define AZI_C 0.006135923151542565f
#define INC_C 0.008267349088394194f

// scratch (device globals; no runtime alloc)
__device__ __half g_UTh[(size_t)NPIX * 64];   // pixel-major U  [pix][64] fp16
__device__ __half g_VTh[(size_t)NPIX * 64];   // pixel-major V' [pix][64] fp16
__device__ float g_mean[128], g_rstd[128];
__device__ float2 g_part[1024];
__device__ float2 g_pp[128 * 512];            // per-CTA group partials (layer2 stats)

// ---------------- helpers ----------------
__device__ __forceinline__ uint32_t smem_u32(const void* p) {
    uint32_t a;
    asm("{ .reg .u64 t; cvta.to.shared.u64 t, %1; cvt.u32.u64 %0, t; }" : "=r"(a) : "l"(p));
    return a;
}
#define LDSM4(r0, r1, r2, r3, a) \
    asm volatile("ldmatrix.sync.aligned.m8n8.x4.shared.b16 {%0,%1,%2,%3}, [%4];" \
        : "=r"(r0), "=r"(r1), "=r"(r2), "=r"(r3) : "r"(a))
#define MMAF16(c0, c1, c2, c3, a0, a1, a2, a3, b0, b1) \
    asm volatile("mma.sync.aligned.m16n8k16.row.col.f32.f16.f16.f32 " \
        "{%0,%1,%2,%3},{%4,%5,%6,%7},{%8,%9},{%0,%1,%2,%3};" \
        : "+f"(c0), "+f"(c1), "+f"(c2), "+f"(c3) \
        : "r"(a0), "r"(a1), "r"(a2), "r"(a3), "r"(b0), "r"(b1))

// swizzled tile addressing: pitch 128B, chunk = 16B unit
__device__ __forceinline__ uint32_t swadr(int row, int chunk) {
    return (uint32_t)(row * 128 + ((chunk ^ (row & 7)) << 4));
}

// ---------------- GroupNorm stats (layer 1), two-phase ----------------
__global__ void gn_part_kernel(const float* __restrict__ in) {
    int c = blockIdx.x, t = threadIdx.x;
    const float4* base = reinterpret_cast<const float4*>(in + (size_t)c * 16384);
    float s = 0.f, q = 0.f;
    for (int i = t; i < 4096; i += 256) {
        float4 v = base[i];
        s += (v.x + v.y) + (v.z + v.w);
        q += (v.x * v.x + v.y * v.y) + (v.z * v.z + v.w * v.w);
    }
    __shared__ float rs[256], rq[256];
    rs[t] = s; rq[t] = q;
    __syncthreads();
    for (int off = 128; off > 0; off >>= 1) {
        if (t < off) { rs[t] += rs[t + off]; rq[t] += rq[t + off]; }
        __syncthreads();
    }
    if (t == 0) g_part[c] = make_float2(rs[0], rq[0]);
}
__global__ void gn_fin_kernel() {
    int t = threadIdx.x;
    if (t < 128) {
        float s = 0.f, q = 0.f;
#pragma unroll
        for (int i = 0; i < 8; i++) { float2 p = g_part[t * 8 + i]; s += p.x; q += p.y; }
        float m = s * (1.f / 131072.f);
        g_mean[t] = m;
        g_rstd[t] = rsqrtf(q * (1.f / 131072.f) - m * m + 1e-6f);
    }
}
// layer-2 stats finalize from per-CTA partials written by edge1
__global__ void gn_fin2_kernel() {
    int bg = blockIdx.x, t = threadIdx.x;
    __shared__ float ss[256], sq2[256];
    float2 a = g_pp[bg * 512 + t];
    float2 c = g_pp[bg * 512 + 256 + t];
    ss[t]  = a.x + c.x;
    sq2[t] = a.y + c.y;
    __syncthreads();
    for (int off = 128; off > 0; off >>= 1) {
        if (t < off) { ss[t] += ss[t + off]; sq2[t] += sq2[t + off]; }
        __syncthreads();
    }
    if (t == 0) {
        float m = ss[0] * (1.f / 131072.f);
        g_mean[bg] = m;
        g_rstd[bg] = rsqrtf(sq2[0] * (1.f / 131072.f) - m * m + 1e-6f);
    }
}

// ---------------- GEMM1: U,V' = relu(gn(x)) @ [Wa;Wb]^T (fp16, M32xN64 warp tile) ----------------
#define GA   0
#define GB   16384
#define G_CF 32768
#define G_SZ 33792

__global__ __launch_bounds__(256, 2) void gemm_mm_kernel(
    const float* __restrict__ xin, const float* __restrict__ r,
    const float* __restrict__ w1, const float* __restrict__ b1,
    const float* __restrict__ gnw, const float* __restrict__ gnb)
{
    extern __shared__ char smc[];
    uint32_t sb = smem_u32(smc);
    float* scf  = (float*)(smc + G_CF);
    float* bif  = scf + 64;
    float* b1f  = scf + 128;
    float* wp0f = scf + 192;

    int t = threadIdx.x, wid = t >> 5, ln = t & 31;
    int p0 = blockIdx.x << 7;
    int b = p0 >> 16, pl = p0 & 65535;

    if (t < 64) {
        int grp = (b << 5) + (t >> 1);
        float sc = g_rstd[grp] * gnw[t];
        scf[t]  = sc;
        bif[t]  = gnb[t] - g_mean[grp] * sc;
        b1f[t]  = b1[t];
        wp0f[t] = w1[t * 131 + 128];
    }
    // B = [Wa;Wb] fp16, swizzled
    for (int e = t; e < 8192; e += 256) {
        int n = e >> 6, k = e & 63;
        float v = (n < 64) ? w1[n * 131 + k] : w1[(n - 64) * 131 + 64 + k];
        *(__half*)(smc + GB + swadr(n, k >> 3) + (k & 7) * 2) = __float2half_rn(v);
    }
    {
        int p = t & 127, co = (t >> 7) << 5;
        const float* xb = xin + (((size_t)(b * 64 + co)) << 16) + pl + p;
#pragma unroll
        for (int kc = 0; kc < 4; kc++) {
            float xv[8];
#pragma unroll
            for (int i = 0; i < 8; i++) {
                int k = co + kc * 8 + i;
                float raw = xb[((size_t)(kc * 8 + i)) << 16];
                xv[i] = fmaxf(fmaf(raw, scf[k], bif[k]), 0.f);
            }
            __half2 h0 = __floats2half2_rn(xv[0], xv[1]);
            __half2 h1 = __floats2half2_rn(xv[2], xv[3]);
            __half2 h2 = __floats2half2_rn(xv[4], xv[5]);
            __half2 h3 = __floats2half2_rn(xv[6], xv[7]);
            *(uint4*)(smc + GA + swadr(p, (co >> 3) + kc)) = make_uint4(
                *reinterpret_cast<uint32_t*>(&h0), *reinterpret_cast<uint32_t*>(&h1),
                *reinterpret_cast<uint32_t*>(&h2), *reinterpret_cast<uint32_t*>(&h3));
        }
    }
    __syncthreads();

    // warp tile: M32 pixels (mi = wid&3) x N64 channels (ni = wid>>2)
    int mi = wid & 3, ni = wid >> 2;
    float acc[2][8][4];
#pragma unroll
    for (int m = 0; m < 2; m++)
#pragma unroll
        for (int nb = 0; nb < 8; nb++)
#pragma unroll
            for (int j = 0; j < 4; j++) acc[m][nb][j] = 0.f;

#pragma unroll
    for (int kh = 0; kh < 2; kh++) {
        uint32_t ah[2][8];
#pragma unroll
        for (int m = 0; m < 2; m++) {
            int row = mi * 32 + m * 16 + (ln & 15);
            int c0 = kh * 4 + (ln >> 4);
            LDSM4(ah[m][0], ah[m][1], ah[m][2], ah[m][3], sb + GA + swadr(row, c0));
            LDSM4(ah[m][4], ah[m][5], ah[m][6], ah[m][7], sb + GA + swadr(row, c0 + 2));
        }
#pragma unroll
        for (int nb = 0; nb < 8; nb++) {
            int brow = ni * 64 + nb * 8 + (ln & 7);
            int bc = kh * 4 + (ln >> 3);
            uint32_t bh[4];
            LDSM4(bh[0], bh[1], bh[2], bh[3], sb + GB + swadr(brow, bc));
#pragma unroll
            for (int m = 0; m < 2; m++) {
                MMAF16(acc[m][nb][0], acc[m][nb][1], acc[m][nb][2], acc[m][nb][3],
                       ah[m][0], ah[m][1], ah[m][2], ah[m][3], bh[0], bh[1]);
                MMAF16(acc[m][nb][0], acc[m][nb][1], acc[m][nb][2], acc[m][nb][3],
                       ah[m][4], ah[m][5], ah[m][6], ah[m][7], bh[2], bh[3]);
            }
        }
    }

    int cx = (ln & 3) << 1;
#pragma unroll
    for (int m = 0; m < 2; m++) {
        int pr0 = mi * 32 + m * 16 + (ln >> 2), pr1 = pr0 + 8;
        size_t gp0 = (size_t)((b << 16) + pl + pr0);
        size_t gp1 = (size_t)((b << 16) + pl + pr1);
        if (ni == 0) {
#pragma unroll
            for (int nb = 0; nb < 8; nb++) {
                int ch = nb * 8 + cx;
                *(__half2*)(g_UTh + gp0 * 64 + ch) =
                    __floats2half2_rn(acc[m][nb][0], acc[m][nb][1]);
                *(__half2*)(g_UTh + gp1 * 64 + ch) =
                    __floats2half2_rn(acc[m][nb][2], acc[m][nb][3]);
            }
        } else {
            float r0 = r[gp0], r1 = r[gp1];
#pragma unroll
            for (int nb = 0; nb < 8; nb++) {
                int ch = nb * 8 + cx;
                float bb0 = b1f[ch], bb1 = b1f[ch + 1];
                float w0 = wp0f[ch], w1v = wp0f[ch + 1];
                *(__half2*)(g_VTh + gp0 * 64 + ch) =
                    __floats2half2_rn(acc[m][nb][0] + bb0 - r0 * w0,
                                      acc[m][nb][1] + bb1 - r0 * w1v);
                *(__half2*)(g_VTh + gp1 * 64 + ch) =
                    __floats2half2_rn(acc[m][nb][2] + bb0 - r1 * w0,
                                      acc[m][nb][3] + bb1 - r1 * w1v);
            }
        }
    }
}

// ---------------- Edge-max (R12-best config): hoisted w2, half2 build, f32 best ----------------
// ET0 16KB | ET1 16KB | EW 8KB | EV 16KB | EQH (9*64 half) | EB2
#define ET0  0
#define ET1  16384
#define EW   32768
#define EV   40960
#define EQH  57344
#define EB2  58496
#define E_SZ 58752

__global__ __launch_bounds__(256, 2) void edge_mm_kernel(
    const float* __restrict__ r, const float* __restrict__ w1,
    const float* __restrict__ w2, const float* __restrict__ b2,
    const float* __restrict__ xres, float* __restrict__ out, int add_res)
{
    extern __shared__ char smc[];
    uint32_t sb = smem_u32(smc);
    float* sB2 = (float*)(smc + EB2);
    __half* sQh = (__half*)(smc + EQH);

    int t = threadIdx.x, wid = t >> 5, ln = t & 31;
    int p0 = blockIdx.x << 7;
    int b = p0 >> 16, pl = p0 & 65535;
    int w0 = pl >> 10, h0 = pl & 1023;
    int p = t & 127, co = (t >> 7) << 5, co8 = co >> 3;

    // w2 [o][k] fp16 swizzled
    for (int e = t; e < 4096; e += 256) {
        int o = e >> 6, k = e & 63;
        *(__half*)(smc + EW + swadr(o, k >> 3) + (k & 7) * 2) = __float2half_rn(w2[e]);
    }
    {   // V' fp16 -> EV (swizzled)
        const uint4* vsrc = reinterpret_cast<const uint4*>(
            g_VTh + ((size_t)((b << 16) + pl + p)) * 64 + co);
#pragma unroll
        for (int kc = 0; kc < 4; kc++)
            *(uint4*)(smc + EV + swadr(p, co8 + kc)) = vsrc[kc];
    }
    for (int e = t; e < 576; e += 256) {
        int s = e >> 6, k = e & 63;
        int swv = s / 3 - 1, shv = s % 3 - 1;
        float ca = cosf(swv * AZI_C), sa = sinf(swv * AZI_C);
        float ci = cosf(shv * INC_C), si = sinf(shv * INC_C);
        sQh[e] = __float2half_rn(ca * ci * w1[k * 131 + 128]
                               + ca * si * w1[k * 131 + 129]
                               + sa * w1[k * 131 + 130]);
    }
    if (t < 64) sB2[t] = b2[t];
    __syncthreads();

    // hoist w2 A-fragments: warp = (mi: 2 x 32ch, ni: 4 x 32px)
    int mi = wid & 1, ni = wid >> 1;
    uint32_t wa[2][4][4];
#pragma unroll
    for (int m = 0; m < 2; m++) {
        int row = mi * 32 + m * 16 + (ln & 15);
#pragma unroll
        for (int q = 0; q < 4; q++)
            LDSM4(wa[m][q][0], wa[m][q][1], wa[m][q][2], wa[m][q][3],
                  sb + EW + swadr(row, q * 2 + (ln >> 4)));
    }

    const __half2 z2 = __float2half2_rn(0.f);
    // half2 t-build into buffer `base`
    auto buildT = [&](int s, uint32_t base) {
        int swv = s / 3 - 1, shv = s % 3 - 1;
        int wsrc = (w0 - swv) & 63;
        size_t rowb = ((size_t)(b << 16)) + ((size_t)wsrc << 10);
        int hs = (h0 + p - shv) & 1023;
        const uint4* ub = reinterpret_cast<const uint4*>(
            g_UTh + (rowb + hs) * 64 + co);
        __half2 rs2 = __float2half2_rn(__ldg(r + rowb + hs));
        const __half2* qh = reinterpret_cast<const __half2*>(sQh + s * 64 + co);
#pragma unroll
        for (int kc = 0; kc < 4; kc++) {
            uint4 uu = ub[kc];
            uint4 vv = *(const uint4*)(smc + EV + swadr(p, co8 + kc));
            const __half2* u2 = reinterpret_cast<const __half2*>(&uu);
            const __half2* v2 = reinterpret_cast<const __half2*>(&vv);
            uint4 ov;
            __half2* o2 = reinterpret_cast<__half2*>(&ov);
#pragma unroll
            for (int j = 0; j < 4; j++)
                o2[j] = __hmax2(__hfma2(rs2, qh[kc * 4 + j],
                                        __hadd2(u2[j], v2[j])), z2);
            *(uint4*)(smc + base + swadr(p, co8 + kc)) = ov;
        }
    };

    float best[2][4][4];
#pragma unroll
    for (int m = 0; m < 2; m++)
#pragma unroll
        for (int ng = 0; ng < 4; ng++)
#pragma unroll
            for (int j = 0; j < 4; j++) best[m][ng][j] = -1e30f;

    buildT(0, ET0);
    __syncthreads();

    for (int s = 0; s < 9; s++) {
        uint32_t cur = (s & 1) ? ET1 : ET0;
#pragma unroll
        for (int ng = 0; ng < 4; ng++) {
            int rowt = ni * 32 + ng * 8 + (ln & 7);
            uint32_t tb0[4], tb1[4];
            LDSM4(tb0[0], tb0[1], tb0[2], tb0[3], sb + cur + swadr(rowt, (ln >> 3)));
            LDSM4(tb1[0], tb1[1], tb1[2], tb1[3], sb + cur + swadr(rowt, 4 + (ln >> 3)));
            float acc[2][4];
#pragma unroll
            for (int m = 0; m < 2; m++)
#pragma unroll
                for (int j = 0; j < 4; j++) acc[m][j] = 0.f;
#pragma unroll
            for (int m = 0; m < 2; m++) {
                MMAF16(acc[m][0], acc[m][1], acc[m][2], acc[m][3],
                       wa[m][0][0], wa[m][0][1], wa[m][0][2], wa[m][0][3],
                       tb0[0], tb0[1]);
                MMAF16(acc[m][0], acc[m][1], acc[m][2], acc[m][3],
                       wa[m][1][0], wa[m][1][1], wa[m][1][2], wa[m][1][3],
                       tb0[2], tb0[3]);
                MMAF16(acc[m][0], acc[m][1], acc[m][2], acc[m][3],
                       wa[m][2][0], wa[m][2][1], wa[m][2][2], wa[m][2][3],
                       tb1[0], tb1[1]);
                MMAF16(acc[m][0], acc[m][1], acc[m][2], acc[m][3],
                       wa[m][3][0], wa[m][3][1], wa[m][3][2], wa[m][3][3],
                       tb1[2], tb1[3]);
            }
#pragma unroll
            for (int m = 0; m < 2; m++)
#pragma unroll
                for (int j = 0; j < 4; j++)
                    best[m][ng][j] = fmaxf(best[m][ng][j], acc[m][j]);
        }
        if (s < 8) buildT(s + 1, (s & 1) ? ET0 : ET1);
        __syncthreads();
    }

    // epilogue: D frag rows = channels, cols = pixels -> sTr[ch][136], coalesced store
    float* sTr = (float*)smc;    // [64][136] floats = 34816 B (overlays ET0/ET1/EW)
    {
        int cr = ln >> 2, cx2 = (ln & 3) << 1;
#pragma unroll
        for (int m = 0; m < 2; m++) {
            int ch0 = mi * 32 + m * 16 + cr, ch1 = ch0 + 8;
#pragma unroll
            for (int ng = 0; ng < 4; ng++) {
                int px = ni * 32 + ng * 8 + cx2;
                *(float2*)(sTr + ch0 * 136 + px) = make_float2(best[m][ng][0], best[m][ng][1]);
                *(float2*)(sTr + ch1 * 136 + px) = make_float2(best[m][ng][2], best[m][ng][3]);
            }
        }
    }
    __syncthreads();
#pragma unroll
    for (int i = 0; i < 32; i++) {
        int e = t + i * 256;
        int o = e >> 7, pix = e & 127;
        float v = sTr[o * 136 + pix] + sB2[o];
        size_t idx = (((size_t)(b * 64 + o)) << 16) + (pl + pix);
        if (add_res) v += xres[idx];
        out[idx] = v;
    }

    // layer-1 only: per-CTA group partial sums for gn2 (deterministic, no atomics)
    if (!add_res && t < 64) {
        float bias = sB2[t];
        float s = 0.f, q = 0.f;
        const float* row = sTr + t * 136;
#pragma unroll 4
        for (int px = 0; px < 128; px++) {
            float v = row[px] + bias;
            s += v;
            q += v * v;
        }
        s += __shfl_xor_sync(0xffffffffu, s, 1);
        q += __shfl_xor_sync(0xffffffffu, q, 1);
        if ((t & 1) == 0) {
            int g = t >> 1;
            g_pp[((b << 5) + g) * 512 + (blockIdx.x & 511)] = make_float2(s, q);
        }
    }
}

// ---------------------------------------------------------------------------
extern "C" void kernel_launch(void* const* d_in, const int* in_sizes, int n_in,
                              void* d_out, int out_size) {
    const float* x     = (const float*)d_in[0];
    const float* r     = (const float*)d_in[1];
    const float* n1_w  = (const float*)d_in[2];
    const float* n1_b  = (const float*)d_in[3];
    const float* c1_w1 = (const float*)d_in[4];
    const float* c1_b1 = (const float*)d_in[5];
    const float* c1_w2 = (const float*)d_in[6];
    const float* c1_b2 = (const float*)d_in[7];
    const float* n2_w  = (const float*)d_in[8];
    const float* n2_b  = (const float*)d_in[9];
    const float* c2_w1 = (const float*)d_in[10];
    const float* c2_b1 = (const float*)d_in[11];
    const float* c2_w2 = (const float*)d_in[12];
    const float* c2_b2 = (const float*)d_in[13];
    float* out = (float*)d_out;

    cudaFuncSetAttribute(gemm_mm_kernel,
                         cudaFuncAttributeMaxDynamicSharedMemorySize, G_SZ);
    cudaFuncSetAttribute(edge_mm_kernel,
                         cudaFuncAttributeMaxDynamicSharedMemorySize, E_SZ);

    gn_part_kernel<<<1024, 256>>>(x);
    gn_fin_kernel<<<1, 128>>>();
    gemm_mm_kernel<<<2048, 256, G_SZ>>>(x, r, c1_w1, c1_b1, n1_w, n1_b);
    edge_mm_kernel<<<2048, 256, E_SZ>>>(r, c1_w1, c1_w2, c1_b2, nullptr, out, 0);

    gn_fin2_kernel<<<128, 256>>>();
    gemm_mm_kernel<<<2048, 256, G_SZ>>>(out, r, c2_w1, c2_b1, n2_w, n2_b);
    edge_mm_kernel<<<2048, 256, E_SZ>>>(r, c2_w1, c2_w2, c2_b2, x, out, 1);
}

// round 16
// speedup vs baseline: 1.0304x; 1.0304x over previous
#include <cuda_runtime.h>
#include <cuda_bf16.h>
#include <cuda_fp16.h>
#include <cstdint>

#define NPIX 262144
#define AZI_C 0.006135923151542565f
#define INC_C 0.008267349088394194f

// scratch (device globals; no runtime alloc)
__device__ __half g_UTh[(size_t)NPIX * 64];   // pixel-major U  [pix][64] fp16
__device__ __half g_VTh[(size_t)NPIX * 64];   // pixel-major V' [pix][64] fp16
__device__ float g_mean[128], g_rstd[128];
__device__ float2 g_part[1024];
__device__ float2 g_pp[128 * 512];            // per-CTA group partials (layer2 stats)

// ---------------- helpers ----------------
__device__ __forceinline__ uint32_t smem_u32(const void* p) {
    uint32_t a;
    asm("{ .reg .u64 t; cvta.to.shared.u64 t, %1; cvt.u32.u64 %0, t; }" : "=r"(a) : "l"(p));
    return a;
}
#define LDSM4(r0, r1, r2, r3, a) \
    asm volatile("ldmatrix.sync.aligned.m8n8.x4.shared.b16 {%0,%1,%2,%3}, [%4];" \
        : "=r"(r0), "=r"(r1), "=r"(r2), "=r"(r3) : "r"(a))
#define MMAF16(c0, c1, c2, c3, a0, a1, a2, a3, b0, b1) \
    asm volatile("mma.sync.aligned.m16n8k16.row.col.f32.f16.f16.f32 " \
        "{%0,%1,%2,%3},{%4,%5,%6,%7},{%8,%9},{%0,%1,%2,%3};" \
        : "+f"(c0), "+f"(c1), "+f"(c2), "+f"(c3) \
        : "r"(a0), "r"(a1), "r"(a2), "r"(a3), "r"(b0), "r"(b1))

// swizzled tile addressing: pitch 128B, chunk = 16B unit
__device__ __forceinline__ uint32_t swadr(int row, int chunk) {
    return (uint32_t)(row * 128 + ((chunk ^ (row & 7)) << 4));
}

// ---------------- GroupNorm stats (layer 1), two-phase ----------------
__global__ void gn_part_kernel(const float* __restrict__ in) {
    int c = blockIdx.x, t = threadIdx.x;
    const float4* base = reinterpret_cast<const float4*>(in + (size_t)c * 16384);
    float s = 0.f, q = 0.f;
    for (int i = t; i < 4096; i += 256) {
        float4 v = base[i];
        s += (v.x + v.y) + (v.z + v.w);
        q += (v.x * v.x + v.y * v.y) + (v.z * v.z + v.w * v.w);
    }
    __shared__ float rs[256], rq[256];
    rs[t] = s; rq[t] = q;
    __syncthreads();
    for (int off = 128; off > 0; off >>= 1) {
        if (t < off) { rs[t] += rs[t + off]; rq[t] += rq[t + off]; }
        __syncthreads();
    }
    if (t == 0) g_part[c] = make_float2(rs[0], rq[0]);
}
__global__ void gn_fin_kernel() {
    int t = threadIdx.x;
    if (t < 128) {
        float s = 0.f, q = 0.f;
#pragma unroll
        for (int i = 0; i < 8; i++) { float2 p = g_part[t * 8 + i]; s += p.x; q += p.y; }
        float m = s * (1.f / 131072.f);
        g_mean[t] = m;
        g_rstd[t] = rsqrtf(q * (1.f / 131072.f) - m * m + 1e-6f);
    }
}
// layer-2 stats finalize from per-CTA partials written by edge1
__global__ void gn_fin2_kernel() {
    int bg = blockIdx.x, t = threadIdx.x;
    __shared__ float ss[256], sq2[256];
    float2 a = g_pp[bg * 512 + t];
    float2 c = g_pp[bg * 512 + 256 + t];
    ss[t]  = a.x + c.x;
    sq2[t] = a.y + c.y;
    __syncthreads();
    for (int off = 128; off > 0; off >>= 1) {
        if (t < off) { ss[t] += ss[t + off]; sq2[t] += sq2[t + off]; }
        __syncthreads();
    }
    if (t == 0) {
        float m = ss[0] * (1.f / 131072.f);
        g_mean[bg] = m;
        g_rstd[bg] = rsqrtf(sq2[0] * (1.f / 131072.f) - m * m + 1e-6f);
    }
}

// ---------------- GEMM1: U,V' = relu(gn(x)) @ [Wa;Wb]^T (fp16, M32xN64 warp tile) ----------------
#define GA   0
#define GB   16384
#define G_CF 32768
#define G_SZ 33792

__global__ __launch_bounds__(256, 2) void gemm_mm_kernel(
    const float* __restrict__ xin, const float* __restrict__ r,
    const float* __restrict__ w1, const float* __restrict__ b1,
    const float* __restrict__ gnw, const float* __restrict__ gnb)
{
    extern __shared__ char smc[];
    uint32_t sb = smem_u32(smc);
    float* scf  = (float*)(smc + G_CF);
    float* bif  = scf + 64;
    float* b1f  = scf + 128;
    float* wp0f = scf + 192;

    int t = threadIdx.x, wid = t >> 5, ln = t & 31;
    int p0 = blockIdx.x << 7;
    int b = p0 >> 16, pl = p0 & 65535;

    if (t < 64) {
        int grp = (b << 5) + (t >> 1);
        float sc = g_rstd[grp] * gnw[t];
        scf[t]  = sc;
        bif[t]  = gnb[t] - g_mean[grp] * sc;
        b1f[t]  = b1[t];
        wp0f[t] = w1[t * 131 + 128];
    }
    // B = [Wa;Wb] fp16, swizzled
    for (int e = t; e < 8192; e += 256) {
        int n = e >> 6, k = e & 63;
        float v = (n < 64) ? w1[n * 131 + k] : w1[(n - 64) * 131 + 64 + k];
        *(__half*)(smc + GB + swadr(n, k >> 3) + (k & 7) * 2) = __float2half_rn(v);
    }
    {
        int p = t & 127, co = (t >> 7) << 5;
        const float* xb = xin + (((size_t)(b * 64 + co)) << 16) + pl + p;
#pragma unroll
        for (int kc = 0; kc < 4; kc++) {
            float xv[8];
#pragma unroll
            for (int i = 0; i < 8; i++) {
                int k = co + kc * 8 + i;
                float raw = xb[((size_t)(kc * 8 + i)) << 16];
                xv[i] = fmaxf(fmaf(raw, scf[k], bif[k]), 0.f);
            }
            __half2 h0 = __floats2half2_rn(xv[0], xv[1]);
            __half2 h1 = __floats2half2_rn(xv[2], xv[3]);
            __half2 h2 = __floats2half2_rn(xv[4], xv[5]);
            __half2 h3 = __floats2half2_rn(xv[6], xv[7]);
            *(uint4*)(smc + GA + swadr(p, (co >> 3) + kc)) = make_uint4(
                *reinterpret_cast<uint32_t*>(&h0), *reinterpret_cast<uint32_t*>(&h1),
                *reinterpret_cast<uint32_t*>(&h2), *reinterpret_cast<uint32_t*>(&h3));
        }
    }
    __syncthreads();

    // warp tile: M32 pixels (mi = wid&3) x N64 channels (ni = wid>>2)
    int mi = wid & 3, ni = wid >> 2;
    float acc[2][8][4];
#pragma unroll
    for (int m = 0; m < 2; m++)
#pragma unroll
        for (int nb = 0; nb < 8; nb++)
#pragma unroll
            for (int j = 0; j < 4; j++) acc[m][nb][j] = 0.f;

#pragma unroll
    for (int kh = 0; kh < 2; kh++) {
        uint32_t ah[2][8];
#pragma unroll
        for (int m = 0; m < 2; m++) {
            int row = mi * 32 + m * 16 + (ln & 15);
            int c0 = kh * 4 + (ln >> 4);
            LDSM4(ah[m][0], ah[m][1], ah[m][2], ah[m][3], sb + GA + swadr(row, c0));
            LDSM4(ah[m][4], ah[m][5], ah[m][6], ah[m][7], sb + GA + swadr(row, c0 + 2));
        }
#pragma unroll
        for (int nb = 0; nb < 8; nb++) {
            int brow = ni * 64 + nb * 8 + (ln & 7);
            int bc = kh * 4 + (ln >> 3);
            uint32_t bh[4];
            LDSM4(bh[0], bh[1], bh[2], bh[3], sb + GB + swadr(brow, bc));
#pragma unroll
            for (int m = 0; m < 2; m++) {
                MMAF16(acc[m][nb][0], acc[m][nb][1], acc[m][nb][2], acc[m][nb][3],
                       ah[m][0], ah[m][1], ah[m][2], ah[m][3], bh[0], bh[1]);
                MMAF16(acc[m][nb][0], acc[m][nb][1], acc[m][nb][2], acc[m][nb][3],
                       ah[m][4], ah[m][5], ah[m][6], ah[m][7], bh[2], bh[3]);
            }
        }
    }

    int cx = (ln & 3) << 1;
#pragma unroll
    for (int m = 0; m < 2; m++) {
        int pr0 = mi * 32 + m * 16 + (ln >> 2), pr1 = pr0 + 8;
        size_t gp0 = (size_t)((b << 16) + pl + pr0);
        size_t gp1 = (size_t)((b << 16) + pl + pr1);
        if (ni == 0) {
#pragma unroll
            for (int nb = 0; nb < 8; nb++) {
                int ch = nb * 8 + cx;
                *(__half2*)(g_UTh + gp0 * 64 + ch) =
                    __floats2half2_rn(acc[m][nb][0], acc[m][nb][1]);
                *(__half2*)(g_UTh + gp1 * 64 + ch) =
                    __floats2half2_rn(acc[m][nb][2], acc[m][nb][3]);
            }
        } else {
            float r0 = r[gp0], r1 = r[gp1];
#pragma unroll
            for (int nb = 0; nb < 8; nb++) {
                int ch = nb * 8 + cx;
                float bb0 = b1f[ch], bb1 = b1f[ch + 1];
                float w0 = wp0f[ch], w1v = wp0f[ch + 1];
                *(__half2*)(g_VTh + gp0 * 64 + ch) =
                    __floats2half2_rn(acc[m][nb][0] + bb0 - r0 * w0,
                                      acc[m][nb][1] + bb1 - r0 * w1v);
                *(__half2*)(g_VTh + gp1 * 64 + ch) =
                    __floats2half2_rn(acc[m][nb][2] + bb0 - r1 * w0,
                                      acc[m][nb][3] + bb1 - r1 * w1v);
            }
        }
    }
}

// ---------------- Edge-max (R13 config): hoisted w2, V' in regs, half2 build/best ----------------
// ET0 16KB | ET1 16KB | EW 8KB | EQH (9*64 half) | EB2
#define ET0  0
#define ET1  16384
#define EW   32768
#define EQH  40960
#define EB2  42112
#define E_SZ 42368

__global__ __launch_bounds__(256, 2) void edge_mm_kernel(
    const float* __restrict__ r, const float* __restrict__ w1,
    const float* __restrict__ w2, const float* __restrict__ b2,
    const float* __restrict__ xres, float* __restrict__ out, int add_res)
{
    extern __shared__ char smc[];
    uint32_t sb = smem_u32(smc);
    float* sB2 = (float*)(smc + EB2);
    __half* sQh = (__half*)(smc + EQH);

    int t = threadIdx.x, wid = t >> 5, ln = t & 31;
    int p0 = blockIdx.x << 7;
    int b = p0 >> 16, pl = p0 & 65535;
    int w0 = pl >> 10, h0 = pl & 1023;
    int p = t & 127, co = (t >> 7) << 5, co8 = co >> 3;

    // w2 [o][k] fp16 swizzled
    for (int e = t; e < 4096; e += 256) {
        int o = e >> 6, k = e & 63;
        *(__half*)(smc + EW + swadr(o, k >> 3) + (k & 7) * 2) = __float2half_rn(w2[e]);
    }
    // V' -> registers (16 regs as 4 x uint4)
    uint4 vR[4];
    {
        const uint4* vsrc = reinterpret_cast<const uint4*>(
            g_VTh + ((size_t)((b << 16) + pl + p)) * 64 + co);
#pragma unroll
        for (int kc = 0; kc < 4; kc++) vR[kc] = vsrc[kc];
    }
    for (int e = t; e < 576; e += 256) {
        int s = e >> 6, k = e & 63;
        int swv = s / 3 - 1, shv = s % 3 - 1;
        float ca = cosf(swv * AZI_C), sa = sinf(swv * AZI_C);
        float ci = cosf(shv * INC_C), si = sinf(shv * INC_C);
        sQh[e] = __float2half_rn(ca * ci * w1[k * 131 + 128]
                               + ca * si * w1[k * 131 + 129]
                               + sa * w1[k * 131 + 130]);
    }
    if (t < 64) sB2[t] = b2[t];
    __syncthreads();

    // hoist w2 A-fragments: warp = (mi: 2 x 32ch, ni: 4 x 32px)
    int mi = wid & 1, ni = wid >> 1;
    uint32_t wa[2][4][4];
#pragma unroll
    for (int m = 0; m < 2; m++) {
        int row = mi * 32 + m * 16 + (ln & 15);
#pragma unroll
        for (int q = 0; q < 4; q++)
            LDSM4(wa[m][q][0], wa[m][q][1], wa[m][q][2], wa[m][q][3],
                  sb + EW + swadr(row, q * 2 + (ln >> 4)));
    }

    const __half2 z2 = __float2half2_rn(0.f);
    // half2 t-build into buffer `base`
    auto buildT = [&](int s, uint32_t base) {
        int swv = s / 3 - 1, shv = s % 3 - 1;
        int wsrc = (w0 - swv) & 63;
        size_t rowb = ((size_t)(b << 16)) + ((size_t)wsrc << 10);
        int hs = (h0 + p - shv) & 1023;
        const uint4* ub = reinterpret_cast<const uint4*>(
            g_UTh + (rowb + hs) * 64 + co);
        __half2 rs2 = __float2half2_rn(__ldg(r + rowb + hs));
        const __half2* qh = reinterpret_cast<const __half2*>(sQh + s * 64 + co);
#pragma unroll
        for (int kc = 0; kc < 4; kc++) {
            uint4 uu = ub[kc];
            const __half2* u2 = reinterpret_cast<const __half2*>(&uu);
            const __half2* v2 = reinterpret_cast<const __half2*>(&vR[kc]);
            uint4 ov;
            __half2* o2 = reinterpret_cast<__half2*>(&ov);
#pragma unroll
            for (int j = 0; j < 4; j++)
                o2[j] = __hmax2(__hfma2(rs2, qh[kc * 4 + j],
                                        __hadd2(u2[j], v2[j])), z2);
            *(uint4*)(smc + base + swadr(p, co8 + kc)) = ov;
        }
    };

    __half2 bestH[2][4][2];
    const __half2 ninf = __float2half2_rn(-65504.f);
#pragma unroll
    for (int m = 0; m < 2; m++)
#pragma unroll
        for (int ng = 0; ng < 4; ng++) {
            bestH[m][ng][0] = ninf;
            bestH[m][ng][1] = ninf;
        }

    buildT(0, ET0);
    __syncthreads();

    for (int s = 0; s < 9; s++) {
        uint32_t cur = (s & 1) ? ET1 : ET0;
#pragma unroll
        for (int ng = 0; ng < 4; ng++) {
            int rowt = ni * 32 + ng * 8 + (ln & 7);
            uint32_t tb0[4], tb1[4];
            LDSM4(tb0[0], tb0[1], tb0[2], tb0[3], sb + cur + swadr(rowt, (ln >> 3)));
            LDSM4(tb1[0], tb1[1], tb1[2], tb1[3], sb + cur + swadr(rowt, 4 + (ln >> 3)));
            float acc[2][4];
#pragma unroll
            for (int m = 0; m < 2; m++)
#pragma unroll
                for (int j = 0; j < 4; j++) acc[m][j] = 0.f;
#pragma unroll
            for (int m = 0; m < 2; m++) {
                MMAF16(acc[m][0], acc[m][1], acc[m][2], acc[m][3],
                       wa[m][0][0], wa[m][0][1], wa[m][0][2], wa[m][0][3],
                       tb0[0], tb0[1]);
                MMAF16(acc[m][0], acc[m][1], acc[m][2], acc[m][3],
                       wa[m][1][0], wa[m][1][1], wa[m][1][2], wa[m][1][3],
                       tb0[2], tb0[3]);
                MMAF16(acc[m][0], acc[m][1], acc[m][2], acc[m][3],
                       wa[m][2][0], wa[m][2][1], wa[m][2][2], wa[m][2][3],
                       tb1[0], tb1[1]);
                MMAF16(acc[m][0], acc[m][1], acc[m][2], acc[m][3],
                       wa[m][3][0], wa[m][3][1], wa[m][3][2], wa[m][3][3],
                       tb1[2], tb1[3]);
            }
#pragma unroll
            for (int m = 0; m < 2; m++) {
                bestH[m][ng][0] = __hmax2(bestH[m][ng][0],
                                          __floats2half2_rn(acc[m][0], acc[m][1]));
                bestH[m][ng][1] = __hmax2(bestH[m][ng][1],
                                          __floats2half2_rn(acc[m][2], acc[m][3]));
            }
        }
        if (s < 8) buildT(s + 1, (s & 1) ? ET0 : ET1);
        __syncthreads();
    }

    // epilogue: D frag rows = channels, cols = pixels -> sTr[ch][136], coalesced store
    float* sTr = (float*)smc;    // [64][136] floats = 34816 B (overlays ET0/ET1/EW)
    {
        int cr = ln >> 2, cx2 = (ln & 3) << 1;
#pragma unroll
        for (int m = 0; m < 2; m++) {
            int ch0 = mi * 32 + m * 16 + cr, ch1 = ch0 + 8;
#pragma unroll
            for (int ng = 0; ng < 4; ng++) {
                int px = ni * 32 + ng * 8 + cx2;
                float2 f0 = __half22float2(bestH[m][ng][0]);
                float2 f1 = __half22float2(bestH[m][ng][1]);
                *(float2*)(sTr + ch0 * 136 + px) = f0;
                *(float2*)(sTr + ch1 * 136 + px) = f1;
            }
        }
    }
    __syncthreads();
#pragma unroll
    for (int i = 0; i < 32; i++) {
        int e = t + i * 256;
        int o = e >> 7, pix = e & 127;
        float v = sTr[o * 136 + pix] + sB2[o];
        size_t idx = (((size_t)(b * 64 + o)) << 16) + (pl + pix);
        if (add_res) v += xres[idx];
        out[idx] = v;
    }

    // layer-1 only: per-CTA group partial sums for gn2 (deterministic, no atomics)
    if (!add_res && t < 64) {
        float bias = sB2[t];
        float s = 0.f, q = 0.f;
        const float* row = sTr + t * 136;
#pragma unroll 4
        for (int px = 0; px < 128; px++) {
            float v = row[px] + bias;
            s += v;
            q += v * v;
        }
        s += __shfl_xor_sync(0xffffffffu, s, 1);
        q += __shfl_xor_sync(0xffffffffu, q, 1);
        if ((t & 1) == 0) {
            int g = t >> 1;
            g_pp[((b << 5) + g) * 512 + (blockIdx.x & 511)] = make_float2(s, q);
        }
    }
}

// ---------------------------------------------------------------------------
extern "C" void kernel_launch(void* const* d_in, const int* in_sizes, int n_in,
                              void* d_out, int out_size) {
    const float* x     = (const float*)d_in[0];
    const float* r     = (const float*)d_in[1];
    const float* n1_w  = (const float*)d_in[2];
    const float* n1_b  = (const float*)d_in[3];
    const float* c1_w1 = (const float*)d_in[4];
    const float* c1_b1 = (const float*)d_in[5];
    const float* c1_w2 = (const float*)d_in[6];
    const float* c1_b2 = (const float*)d_in[7];
    const float* n2_w  = (const float*)d_in[8];
    const float* n2_b  = (const float*)d_in[9];
    const float* c2_w1 = (const float*)d_in[10];
    const float* c2_b1 = (const float*)d_in[11];
    const float* c2_w2 = (const float*)d_in[12];
    const float* c2_b2 = (const float*)d_in[13];
    float* out = (float*)d_out;

    cudaFuncSetAttribute(gemm_mm_kernel,
                         cudaFuncAttributeMaxDynamicSharedMemorySize, G_SZ);
    cudaFuncSetAttribute(edge_mm_kernel,
                         cudaFuncAttributeMaxDynamicSharedMemorySize, E_SZ);

    gn_part_kernel<<<1024, 256>>>(x);
    gn_fin_kernel<<<1, 128>>>();
    gemm_mm_kernel<<<2048, 256, G_SZ>>>(x, r, c1_w1, c1_b1, n1_w, n1_b);
    edge_mm_kernel<<<2048, 256, E_SZ>>>(r, c1_w1, c1_w2, c1_b2, nullptr, out, 0);

    gn_fin2_kernel<<<128, 256>>>();
    gemm_mm_kernel<<<2048, 256, G_SZ>>>(out, r, c2_w1, c2_b1, n2_w, n2_b);
    edge_mm_kernel<<<2048, 256, E_SZ>>>(r, c2_w1, c2_w2, c2_b2, x, out, 1);
}